// round 17
// baseline (speedup 1.0000x reference)
#include <cuda_runtime.h>
#include <cuda_bf16.h>
#include <cstdint>

// ---------------------------------------------------------------------------
// 2-layer GRU (H=32, INPUT=4, B=4096, S=512) + FC(32->32) + FC(32->1)
//
// R11 structure (best measured: 1103 us), plus:
//  - per-CTA start skew (dependent-FMA delay, (bid*37)&7 buckets) to de-phase
//    co-resident CTAs so gate-tail bubbles of one warp overlap the FMA burst
//    of the SMSP's other warp;
//  - cp.async16 ring fills (1/4 the LDGSTS instructions of cp.async4).
// Math ordering identical to R11 (rel_err 3.8e-5).
// ---------------------------------------------------------------------------

#define B_ROWS 4096
#define SEQ    512
#define HID    32
#define RING   8
#define NWARP  (B_ROWS / 2)       // 2048 warps, 2 rows each

typedef unsigned long long ull;

__device__ float g_h1[(size_t)B_ROWS * SEQ * HID];   // 268 MB scratch

__device__ __forceinline__ ull ffma2(ull a, ull b, ull c) {
    ull d;
    asm("fma.rn.f32x2 %0, %1, %2, %3;" : "=l"(d) : "l"(a), "l"(b), "l"(c));
    return d;
}
__device__ __forceinline__ float hsum2(ull v) {
    float2 r;
    asm("mov.b64 {%0, %1}, %2;" : "=f"(r.x), "=f"(r.y) : "l"(v));
    return r.x + r.y;
}
__device__ __forceinline__ float tanh_ap(float x) {
    float y;
    asm("tanh.approx.f32 %0, %1;" : "=f"(y) : "f"(x));
    return y;
}
__device__ __forceinline__ float sig_ap(float x) {
    return fmaf(0.5f, tanh_ap(0.5f * x), 0.5f);
}
__device__ __forceinline__ void cp_async16(uint32_t smem_addr, const float* gptr) {
    asm volatile("cp.async.ca.shared.global [%0], [%1], 16;"
                 :: "r"(smem_addr), "l"(gptr));
}
__device__ __forceinline__ void cp_commit() {
    asm volatile("cp.async.commit_group;");
}
__device__ __forceinline__ void cp_wait_ring() {
    asm volatile("cp.async.wait_group %0;" :: "n"(RING - 1));
}

// One-time per-CTA phase skew: dependent FMA chain (~160 cyc per bucket).
// Result is kept alive through an impossible-condition store.
__device__ __forceinline__ void phase_skew(float* keepalive) {
    const int sk = (blockIdx.x * 37) & 7;
    float d = 1.0f + (float)sk;
#pragma unroll 1
    for (int i = 0; i < sk * 40; i++)
        d = fmaf(d, 1.0000001f, 0.0000001f);
    if (d < 0.0f) *keepalive = d;     // never true; defeats DCE
}

// ---------------------------------------------------------------------------
// Pass 1: GRU layer 1, 2 rows/warp.  x:[B,S,4] -> h1:[B,S,32]
// ---------------------------------------------------------------------------
__global__ __launch_bounds__(128, 3)
void gru_layer1_kernel(const float* __restrict__ x,
                       const float* __restrict__ Wih,   // [96,4]
                       const float* __restrict__ Whh,   // [96,32]
                       const float* __restrict__ bih,   // [96]
                       const float* __restrict__ bhh)   // [96]
{
    __shared__ __align__(16) float hbuf[4][2][2][HID];
    __shared__ __align__(16) float xring[4][RING][2][4];

    const int warp = (blockIdx.x * blockDim.x + threadIdx.x) >> 5;
    const int wl   = threadIdx.x >> 5;
    const int lane = threadIdx.x & 31;
    if (warp >= NWARP) return;

    const int r0 = warp * 2, r1 = warp * 2 + 1;
    const float* xs0 = x + (size_t)r0 * SEQ * 4;
    const float* xs1 = x + (size_t)r1 * SEQ * 4;

    const uint32_t ring_base =
        (uint32_t)__cvta_generic_to_shared(&xring[wl][0][0][0]);

    // Ring fill: lane 0 -> row0's 16B, lane 1 -> row1's 16B.
    const float* xg16 = (lane == 0) ? xs0 : xs1;

#pragma unroll
    for (int d = 0; d < RING; d++) {
        if (lane < 2) cp_async16(ring_base + d * 32 + lane * 16, xg16 + d * 4);
        cp_commit();
    }

    phase_skew(&hbuf[wl][0][0][0]);   // de-phase co-resident CTAs

    ull whr[16], whz[16], whn[16];
    {
        const ull* pr = reinterpret_cast<const ull*>(Whh + (lane)      * HID);
        const ull* pz = reinterpret_cast<const ull*>(Whh + (32 + lane) * HID);
        const ull* pn = reinterpret_cast<const ull*>(Whh + (64 + lane) * HID);
#pragma unroll
        for (int k = 0; k < 16; k++) { whr[k] = pr[k]; whz[k] = pz[k]; whn[k] = pn[k]; }
    }
    const float4 wir = reinterpret_cast<const float4*>(Wih)[lane];
    const float4 wiz = reinterpret_cast<const float4*>(Wih)[32 + lane];
    const float4 win = reinterpret_cast<const float4*>(Wih)[64 + lane];

    const float br  = bih[lane]      + bhh[lane];
    const float bz  = bih[32 + lane] + bhh[32 + lane];
    const float bin = bih[64 + lane];
    const float bhn = bhh[64 + lane];

    float* op0 = g_h1 + (size_t)r0 * SEQ * HID + lane;
    float* op1 = g_h1 + (size_t)r1 * SEQ * HID + lane;

    float h0 = 0.0f, h1 = 0.0f;
#pragma unroll 1
    for (int s = 0; s < SEQ; s++) {
        hbuf[wl][s & 1][0][lane] = h0;
        hbuf[wl][s & 1][1][lane] = h1;
        cp_wait_ring();
        __syncwarp();

        const float4 xv0 =
            *reinterpret_cast<const float4*>(&xring[wl][s & (RING - 1)][0][0]);
        const float4 xv1 =
            *reinterpret_cast<const float4*>(&xring[wl][s & (RING - 1)][1][0]);
        const ulonglong2* hp0 =
            reinterpret_cast<const ulonglong2*>(&hbuf[wl][s & 1][0][0]);
        const ulonglong2* hp1 =
            reinterpret_cast<const ulonglong2*>(&hbuf[wl][s & 1][1][0]);

        if (lane < 2 && s + RING < SEQ)
            cp_async16(ring_base + ((s + RING) & (RING - 1)) * 32 + lane * 16,
                       xg16 + (s + RING) * 4);
        cp_commit();

        float ar0 = br, az0 = bz, xn0 = bin;
        float ar1 = br, az1 = bz, xn1 = bin;
        ar0 = fmaf(wir.x, xv0.x, ar0); ar0 = fmaf(wir.y, xv0.y, ar0);
        ar0 = fmaf(wir.z, xv0.z, ar0); ar0 = fmaf(wir.w, xv0.w, ar0);
        az0 = fmaf(wiz.x, xv0.x, az0); az0 = fmaf(wiz.y, xv0.y, az0);
        az0 = fmaf(wiz.z, xv0.z, az0); az0 = fmaf(wiz.w, xv0.w, az0);
        xn0 = fmaf(win.x, xv0.x, xn0); xn0 = fmaf(win.y, xv0.y, xn0);
        xn0 = fmaf(win.z, xv0.z, xn0); xn0 = fmaf(win.w, xv0.w, xn0);
        ar1 = fmaf(wir.x, xv1.x, ar1); ar1 = fmaf(wir.y, xv1.y, ar1);
        ar1 = fmaf(wir.z, xv1.z, ar1); ar1 = fmaf(wir.w, xv1.w, ar1);
        az1 = fmaf(wiz.x, xv1.x, az1); az1 = fmaf(wiz.y, xv1.y, az1);
        az1 = fmaf(wiz.z, xv1.z, az1); az1 = fmaf(wiz.w, xv1.w, az1);
        xn1 = fmaf(win.x, xv1.x, xn1); xn1 = fmaf(win.y, xv1.y, xn1);
        xn1 = fmaf(win.z, xv1.z, xn1); xn1 = fmaf(win.w, xv1.w, xn1);

        ull ra0 = 0ull, za0 = 0ull, na0 = 0ull;
        ull ra1 = 0ull, za1 = 0ull, na1 = 0ull;
#pragma unroll
        for (int k = 0; k < 8; k++) {
            const ulonglong2 hv0 = hp0[k];
            const ulonglong2 hv1 = hp1[k];
            ra0 = ffma2(whr[2 * k],     hv0.x, ra0);
            za0 = ffma2(whz[2 * k],     hv0.x, za0);
            na0 = ffma2(whn[2 * k],     hv0.x, na0);
            ra1 = ffma2(whr[2 * k],     hv1.x, ra1);
            za1 = ffma2(whz[2 * k],     hv1.x, za1);
            na1 = ffma2(whn[2 * k],     hv1.x, na1);
            ra0 = ffma2(whr[2 * k + 1], hv0.y, ra0);
            za0 = ffma2(whz[2 * k + 1], hv0.y, za0);
            na0 = ffma2(whn[2 * k + 1], hv0.y, na0);
            ra1 = ffma2(whr[2 * k + 1], hv1.y, ra1);
            za1 = ffma2(whz[2 * k + 1], hv1.y, za1);
            na1 = ffma2(whn[2 * k + 1], hv1.y, na1);
        }
        ar0 += hsum2(ra0);  az0 += hsum2(za0);
        ar1 += hsum2(ra1);  az1 += hsum2(za1);
        const float hn0 = bhn + hsum2(na0);
        const float hn1 = bhn + hsum2(na1);

        const float rr0 = sig_ap(ar0);
        const float zz0 = sig_ap(az0);
        const float nn0 = tanh_ap(fmaf(rr0, hn0, xn0));
        h0 = fmaf(zz0, h0 - nn0, nn0);
        const float rr1 = sig_ap(ar1);
        const float zz1 = sig_ap(az1);
        const float nn1 = tanh_ap(fmaf(rr1, hn1, xn1));
        h1 = fmaf(zz1, h1 - nn1, nn1);

        op0[(size_t)s * HID] = h0;
        op1[(size_t)s * HID] = h1;
    }
}

// ---------------------------------------------------------------------------
// Pass 2: GRU layer 2 + FC, 2 rows/warp.  h1:[B,S,32] -> out:[B]
// ---------------------------------------------------------------------------
__global__ __launch_bounds__(128, 2)
void gru_layer2_fc_kernel(const float* __restrict__ Wih,   // [96,32]
                          const float* __restrict__ Whh,   // [96,32]
                          const float* __restrict__ bih,   // [96]
                          const float* __restrict__ bhh,   // [96]
                          const float* __restrict__ Wfc2,  // [32,32]
                          const float* __restrict__ bfc2,  // [32]
                          const float* __restrict__ Wfc,   // [1,32]
                          const float* __restrict__ bfc,   // [1]
                          float* __restrict__ out)
{
    __shared__ __align__(16) float hbuf[4][2][2][HID];     // [warp][buf][row][unit]
    __shared__ __align__(16) float xring[4][RING][2][HID]; // 256B per slot

    const int warp = (blockIdx.x * blockDim.x + threadIdx.x) >> 5;
    const int wl   = threadIdx.x >> 5;
    const int lane = threadIdx.x & 31;
    if (warp >= NWARP) return;

    const float* xs0 = g_h1 + (size_t)(warp * 2)     * SEQ * HID;
    const float* xs1 = g_h1 + (size_t)(warp * 2 + 1) * SEQ * HID;

    const uint32_t ring_base =
        (uint32_t)__cvta_generic_to_shared(&xring[wl][0][0][0]);

    // Ring fill: lanes 0-7 carry row0's 128B, lanes 8-15 row1's (cp.async16).
    const float* src16 = ((lane < 8) ? xs0 : xs1) + (lane & 7) * 4;

#pragma unroll
    for (int d = 0; d < RING; d++) {
        if (lane < 16)
            cp_async16(ring_base + d * 256 + lane * 16, src16 + d * HID);
        cp_commit();
    }

    phase_skew(&hbuf[wl][0][0][0]);   // de-phase co-resident CTAs

    ull wir[16], wiz[16], win[16], whr[16], whz[16], whn[16];
    {
        const ull* p0 = reinterpret_cast<const ull*>(Wih + (lane)      * HID);
        const ull* p1 = reinterpret_cast<const ull*>(Wih + (32 + lane) * HID);
        const ull* p2 = reinterpret_cast<const ull*>(Wih + (64 + lane) * HID);
        const ull* p3 = reinterpret_cast<const ull*>(Whh + (lane)      * HID);
        const ull* p4 = reinterpret_cast<const ull*>(Whh + (32 + lane) * HID);
        const ull* p5 = reinterpret_cast<const ull*>(Whh + (64 + lane) * HID);
#pragma unroll
        for (int k = 0; k < 16; k++) {
            wir[k] = p0[k]; wiz[k] = p1[k]; win[k] = p2[k];
            whr[k] = p3[k]; whz[k] = p4[k]; whn[k] = p5[k];
        }
    }
    const float br  = bih[lane]      + bhh[lane];
    const float bz  = bih[32 + lane] + bhh[32 + lane];
    const float bin = bih[64 + lane];
    const float bhn = bhh[64 + lane];

    float h0 = 0.0f, h1 = 0.0f;
#pragma unroll 1
    for (int s = 0; s < SEQ; s++) {
        hbuf[wl][s & 1][0][lane] = h0;
        hbuf[wl][s & 1][1][lane] = h1;
        cp_wait_ring();
        __syncwarp();

        const ulonglong2* xp0 =
            reinterpret_cast<const ulonglong2*>(&xring[wl][s & (RING - 1)][0][0]);
        const ulonglong2* xp1 =
            reinterpret_cast<const ulonglong2*>(&xring[wl][s & (RING - 1)][1][0]);
        const ulonglong2* hp0 =
            reinterpret_cast<const ulonglong2*>(&hbuf[wl][s & 1][0][0]);
        const ulonglong2* hp1 =
            reinterpret_cast<const ulonglong2*>(&hbuf[wl][s & 1][1][0]);

        if (lane < 16 && s + RING < SEQ)
            cp_async16(ring_base + ((s + RING) & (RING - 1)) * 256 + lane * 16,
                       src16 + (s + RING) * HID);
        cp_commit();

        ull r0a = 0ull, z0a = 0ull, x0a = 0ull, n0a = 0ull;
        ull r1a = 0ull, z1a = 0ull, x1a = 0ull, n1a = 0ull;
#pragma unroll
        for (int k = 0; k < 8; k++) {
            const ulonglong2 xv0 = xp0[k];
            const ulonglong2 hv0 = hp0[k];
            const ulonglong2 xv1 = xp1[k];
            const ulonglong2 hv1 = hp1[k];
            r0a = ffma2(wir[2 * k],     xv0.x, r0a);
            z0a = ffma2(wiz[2 * k],     xv0.x, z0a);
            x0a = ffma2(win[2 * k],     xv0.x, x0a);
            r0a = ffma2(whr[2 * k],     hv0.x, r0a);
            z0a = ffma2(whz[2 * k],     hv0.x, z0a);
            n0a = ffma2(whn[2 * k],     hv0.x, n0a);
            r1a = ffma2(wir[2 * k],     xv1.x, r1a);
            z1a = ffma2(wiz[2 * k],     xv1.x, z1a);
            x1a = ffma2(win[2 * k],     xv1.x, x1a);
            r1a = ffma2(whr[2 * k],     hv1.x, r1a);
            z1a = ffma2(whz[2 * k],     hv1.x, z1a);
            n1a = ffma2(whn[2 * k],     hv1.x, n1a);
            r0a = ffma2(wir[2 * k + 1], xv0.y, r0a);
            z0a = ffma2(wiz[2 * k + 1], xv0.y, z0a);
            x0a = ffma2(win[2 * k + 1], xv0.y, x0a);
            r0a = ffma2(whr[2 * k + 1], hv0.y, r0a);
            z0a = ffma2(whz[2 * k + 1], hv0.y, z0a);
            n0a = ffma2(whn[2 * k + 1], hv0.y, n0a);
            r1a = ffma2(wir[2 * k + 1], xv1.y, r1a);
            z1a = ffma2(wiz[2 * k + 1], xv1.y, z1a);
            x1a = ffma2(win[2 * k + 1], xv1.y, x1a);
            r1a = ffma2(whr[2 * k + 1], hv1.y, r1a);
            z1a = ffma2(whz[2 * k + 1], hv1.y, z1a);
            n1a = ffma2(whn[2 * k + 1], hv1.y, n1a);
        }
        const float ar0 = br  + hsum2(r0a);
        const float az0 = bz  + hsum2(z0a);
        const float xn0 = bin + hsum2(x0a);
        const float hn0 = bhn + hsum2(n0a);
        const float ar1 = br  + hsum2(r1a);
        const float az1 = bz  + hsum2(z1a);
        const float xn1 = bin + hsum2(x1a);
        const float hn1 = bhn + hsum2(n1a);

        const float rr0 = sig_ap(ar0);
        const float zz0 = sig_ap(az0);
        const float nn0 = tanh_ap(fmaf(rr0, hn0, xn0));
        h0 = fmaf(zz0, h0 - nn0, nn0);
        const float rr1 = sig_ap(ar1);
        const float zz1 = sig_ap(az1);
        const float nn1 = tanh_ap(fmaf(rr1, hn1, xn1));
        h1 = fmaf(zz1, h1 - nn1, nn1);
    }

    // FC2 + FC epilogue for both rows
    {
        hbuf[wl][0][0][lane] = h0;
        hbuf[wl][0][1][lane] = h1;
        __syncwarp();
        const ulonglong2* hp0 =
            reinterpret_cast<const ulonglong2*>(&hbuf[wl][0][0][0]);
        const ulonglong2* hp1 =
            reinterpret_cast<const ulonglong2*>(&hbuf[wl][0][1][0]);
        const ull* wf = reinterpret_cast<const ull*>(Wfc2 + lane * HID);
        ull a0 = 0ull, a1 = 0ull;
#pragma unroll
        for (int k = 0; k < 8; k++) {
            const ulonglong2 hv0 = hp0[k];
            const ulonglong2 hv1 = hp1[k];
            a0 = ffma2(wf[2 * k],     hv0.x, a0);
            a1 = ffma2(wf[2 * k],     hv1.x, a1);
            a0 = ffma2(wf[2 * k + 1], hv0.y, a0);
            a1 = ffma2(wf[2 * k + 1], hv1.y, a1);
        }
        const float bf2 = __ldg(bfc2 + lane);
        const float o0 = bf2 + hsum2(a0);
        const float o1 = bf2 + hsum2(a1);

        const float wfc = __ldg(Wfc + lane);
        float p0 = wfc * o0;
        float p1 = wfc * o1;
#pragma unroll
        for (int off = 16; off > 0; off >>= 1) {
            p0 += __shfl_xor_sync(0xffffffffu, p0, off);
            p1 += __shfl_xor_sync(0xffffffffu, p1, off);
        }
        if (lane == 0) {
            const float bb = __ldg(bfc);
            out[warp * 2]     = p0 + bb;
            out[warp * 2 + 1] = p1 + bb;
        }
    }
}

// ---------------------------------------------------------------------------
// Launch
// ---------------------------------------------------------------------------
extern "C" void kernel_launch(void* const* d_in, const int* in_sizes, int n_in,
                              void* d_out, int out_size)
{
    const float* x     = (const float*)d_in[0];
    const float* Wih0  = (const float*)d_in[1];
    const float* Whh0  = (const float*)d_in[2];
    const float* bih0  = (const float*)d_in[3];
    const float* bhh0  = (const float*)d_in[4];
    const float* Wih1  = (const float*)d_in[5];
    const float* Whh1  = (const float*)d_in[6];
    const float* bih1  = (const float*)d_in[7];
    const float* bhh1  = (const float*)d_in[8];
    const float* Wfc2  = (const float*)d_in[9];
    const float* bfc2  = (const float*)d_in[10];
    const float* Wfc   = (const float*)d_in[11];
    const float* bfc   = (const float*)d_in[12];
    float* out = (float*)d_out;

    const int threads = 128;                 // 4 warps = 8 rows per CTA
    const int blocks  = NWARP / 4;           // 512 CTAs

    gru_layer1_kernel<<<blocks, threads>>>(x, Wih0, Whh0, bih0, bhh0);
    gru_layer2_fc_kernel<<<blocks, threads>>>(Wih1, Whh1, bih1, bhh1,
                                              Wfc2, bfc2, Wfc, bfc, out);
}